// round 16
// baseline (speedup 1.0000x reference)
#include <cuda_runtime.h>
#include <cuda_fp16.h>
#include <cstdint>

// Problem constants
#define NB 16
#define CH 64
#define LL 4096   // H*W
#define DD 1024   // pooled locations
#define CK 8      // C>>3 (theta/phi channels)
#define CG 32     // C>>1 (g channels)

typedef unsigned long long ull;

// Scratch (device globals):
//  g_thetaH[n][l][q]  u32 = f16x2 {theta[2q], theta[2q+1]}, pre-scaled by log2(e)
//  g_phiP  [n][4096]  u32, phi fused-B layout: idx = s*64 + gr*8 + q*2 + u
//  g_gH    [n][j][s*4+q][elem] f16, elem -> d = 16s + {2q,2q+1,2q+8,2q+9}
__device__ __align__(16) uint32_t g_thetaH[NB * LL * 4];   // 4 MB
__device__ __align__(16) uint32_t g_phiP[NB * 4096];       // 256 KB
__device__ __align__(16) __half   g_gH[NB * CG * 1024];    // 1 MB

__device__ __forceinline__ uint32_t pack_h2(float lo, float hi) {
    uint32_t r; asm("cvt.rn.f16x2.f32 %0, %1, %2;" : "=r"(r) : "f"(hi), "f"(lo)); return r;
}
__device__ __forceinline__ uint32_t ex2h2(uint32_t h) {
    uint32_t r; asm("ex2.approx.f16x2 %0, %1;" : "=r"(r) : "r"(h)); return r;
}
__device__ __forceinline__ uint32_t hadd2u(uint32_t a, uint32_t b) {
    uint32_t r; asm("add.f16x2 %0, %1, %2;" : "=r"(r) : "r"(a), "r"(b)); return r;
}
__device__ __forceinline__ float h2sum(uint32_t h) {
    __half2 v = *(__half2*)&h;
    float2 f = __half22float2(v);
    return f.x + f.y;
}

// MMA1: m16n8k8 f16 with f16 accumulator (C=0).
__device__ __forceinline__ void mma_k8_h(uint32_t* d, uint32_t a0, uint32_t a1,
                                         uint32_t b0) {
    asm volatile(
        "mma.sync.aligned.m16n8k8.row.col.f16.f16.f16.f16 "
        "{%0,%1}, {%2,%3}, {%4}, {%5,%6};"
        : "=r"(d[0]), "=r"(d[1])
        : "r"(a0), "r"(a1), "r"(b0), "r"(0u), "r"(0u));
}
// m16n8k16 f16 -> f32 accumulate
__device__ __forceinline__ void mma_k16(float* c, uint32_t a0, uint32_t a1,
                                        uint32_t a2, uint32_t a3,
                                        uint32_t b0, uint32_t b1) {
    asm volatile(
        "mma.sync.aligned.m16n8k16.row.col.f32.f16.f16.f32 "
        "{%0,%1,%2,%3}, {%4,%5,%6,%7}, {%8,%9}, {%0,%1,%2,%3};"
        : "+f"(c[0]), "+f"(c[1]), "+f"(c[2]), "+f"(c[3])
        : "r"(a0), "r"(a1), "r"(a2), "r"(a3), "r"(b0), "r"(b1));
}

// ---------------------------------------------------------------------------
// proj via tensor cores.
// CTA: 512 threads, 512 locations (8 y-rows x 64 x). Grid: 128 CTAs.
// Phase 1: stage x tile -> smem f16 [loc][66] (transposed), W -> [48][66].
// Phase 2: warp w: (p = w>>2, xt = w&3): two m16 tiles (yy=2p, 2p+1) x 16 x.
//          12 MMAs per k-step (6 n-blocks x 2 tiles, shared B fragments).
// Phase 3: theta stored from D fragments; phi/g 2x2-pooled in fragment space
//          (y across tiles in regs, x via shfl_xor(4)), scattered stores.
// smem: 512*66 + 48*66 halves = 73920 B.
// ---------------------------------------------------------------------------
#define XPAD 66
#define PROJ_SMEM (512 * XPAD * 2 + 48 * XPAD * 2)

__global__ void __launch_bounds__(512, 1) proj_mma_kernel(
        const float* __restrict__ x, const float* __restrict__ w_theta,
        const float* __restrict__ w_phi, const float* __restrict__ w_g) {
    extern __shared__ __half sm[];
    __half* x_sh = sm;                    // [512][66]
    __half* W_sh = sm + 512 * XPAD;       // [48][66]

    int tid = threadIdx.x;
    int bid = blockIdx.x;
    int n = bid >> 3, yt = bid & 7;

    // Stage weights (theta rows pre-scaled by log2 e)
    for (int i = tid; i < 48 * 64; i += 512) {
        int oc = i >> 6, c = i & 63;
        float w;
        if (oc < 8)       w = w_theta[oc * 64 + c] * 1.4426950408889634f;
        else if (oc < 16) w = w_phi[(oc - 8) * 64 + c];
        else              w = w_g[(oc - 16) * 64 + c];
        W_sh[oc * XPAD + c] = __float2half_rn(w);
    }

    // Stage x: thread = local loc; l_global = yt*512 + tid
    {
        const float* xp = x + ((size_t)n * CH) * LL + yt * 512 + tid;
        uint32_t* row = (uint32_t*)(x_sh + tid * XPAD);
#pragma unroll 16
        for (int c = 0; c < 64; c += 2) {
            float v0 = xp[(size_t)c * LL];
            float v1 = xp[(size_t)(c + 1) * LL];
            row[c >> 1] = pack_h2(v0, v1);
        }
    }
    __syncthreads();

    int warp = tid >> 5, lane = tid & 31;
    int gr = lane >> 2, q = lane & 3;
    int p = warp >> 2, xt = warp & 3;

    int base0 = (2 * p) * 64 + xt * 16;       // tile0 local row0
    int base1 = base0 + 64;                    // tile1 (yy = 2p+1)

    float acc[2][6][4];
#pragma unroll
    for (int t = 0; t < 2; t++)
#pragma unroll
        for (int nb = 0; nb < 6; nb++)
#pragma unroll
            for (int i = 0; i < 4; i++) acc[t][nb][i] = 0.f;

    const __half* a00 = x_sh + (base0 + gr) * XPAD + 2 * q;
    const __half* a01 = x_sh + (base0 + gr + 8) * XPAD + 2 * q;
    const __half* a10 = x_sh + (base1 + gr) * XPAD + 2 * q;
    const __half* a11 = x_sh + (base1 + gr + 8) * XPAD + 2 * q;
    const __half* wb = W_sh + gr * XPAD + 2 * q;

#pragma unroll
    for (int ks = 0; ks < 4; ks++) {
        int ko = 16 * ks;
        uint32_t A0a = *(const uint32_t*)(a00 + ko);
        uint32_t A0b = *(const uint32_t*)(a01 + ko);
        uint32_t A0c = *(const uint32_t*)(a00 + ko + 8);
        uint32_t A0d = *(const uint32_t*)(a01 + ko + 8);
        uint32_t A1a = *(const uint32_t*)(a10 + ko);
        uint32_t A1b = *(const uint32_t*)(a11 + ko);
        uint32_t A1c = *(const uint32_t*)(a10 + ko + 8);
        uint32_t A1d = *(const uint32_t*)(a11 + ko + 8);
#pragma unroll
        for (int nb = 0; nb < 6; nb++) {
            const __half* wr = wb + (nb * 8) * XPAD + ko;
            uint32_t b0 = *(const uint32_t*)(wr);
            uint32_t b1 = *(const uint32_t*)(wr + 8);
            mma_k16(acc[0][nb], A0a, A0b, A0c, A0d, b0, b1);
            mma_k16(acc[1][nb], A1a, A1b, A1c, A1d, b0, b1);
        }
    }

    // theta stores (nb = 0): both tiles, rows gr and gr+8
#pragma unroll
    for (int t = 0; t < 2; t++) {
        int lloc = (t == 0 ? base0 : base1) + gr;
        size_t L = (size_t)n * LL + yt * 512 + lloc;
        g_thetaH[L * 4 + q]       = pack_h2(acc[t][0][0], acc[t][0][1]);
        g_thetaH[(L + 8) * 4 + q] = pack_h2(acc[t][0][2], acc[t][0][3]);
    }

    // 2x2 pool for phi/g: y across tiles (regs), x across gr pairs (shfl 4)
    float mm[5][4];
#pragma unroll
    for (int nb = 0; nb < 5; nb++) {
#pragma unroll
        for (int i = 0; i < 4; i++) {
            float m = fmaxf(acc[0][nb + 1][i], acc[1][nb + 1][i]);
            float o = __shfl_xor_sync(0xffffffffu, m, 4);
            mm[nb][i] = fmaxf(m, o);
        }
    }

    if ((gr & 1) == 0) {
        // pooled cols: row gr -> dd0, row gr+8 -> dd0+4
        int dd0 = (yt * 4 + p) * 32 + xt * 8 + (gr >> 1);
#pragma unroll
        for (int rr = 0; rr < 2; rr++) {
            int dd = dd0 + rr * 4;
            int s = dd >> 4, r = dd & 15;
            int gra = r & 7, u = r >> 3;
            float v0 = mm[0][2 * rr], v1 = mm[0][2 * rr + 1];
            g_phiP[(size_t)n * 4096 + s * 64 + gra * 8 + q * 2 + u] = pack_h2(v0, v1);

            int qf = (r & 7) >> 1;
            int elem = (r >> 3) * 2 + (r & 1);
            __half* gd = g_gH + (size_t)n * 32768;
#pragma unroll
            for (int nb = 0; nb < 4; nb++) {
                int j0 = nb * 8 + 2 * q;
                gd[((j0 * 256 + s * 4 + qf) << 2) + elem] =
                    __float2half_rn(mm[nb + 1][2 * rr]);
                gd[(((j0 + 1) * 256 + s * 4 + qf) << 2) + elem] =
                    __float2half_rn(mm[nb + 1][2 * rr + 1]);
            }
        }
    }
}

// ---------------------------------------------------------------------------
// Attention kernel: R13 version verbatim (best measured: 32.6 us).
// M=32 per warp, f16 MMA1, row sums on fma pipe, 8 MMA2s/iter,
// fragment-native epilogue. Grid (8, 16) x 512 = 128 CTAs.
// ---------------------------------------------------------------------------
#define SM_PHI 0
#define SM_GA  16384
#define SM_GB  49664
#define SM_WOF 82944
#define SMEM_SZ 88064

__global__ void __launch_bounds__(512, 1) attn_kernel(
        const float* __restrict__ x, const float* __restrict__ w_o,
        const float* __restrict__ gammap, float* __restrict__ out) {
    extern __shared__ char smem[];
    uint32_t* wof = (uint32_t*)(smem + SM_WOF);

    int tid = threadIdx.x;
    int n = blockIdx.y;
    int l0 = blockIdx.x * 512;
    float gamma = *gammap;

    // Cooperative fills
    {
        const uint4* s1 = (const uint4*)(g_phiP + (size_t)n * 4096);
        uint4* d1 = (uint4*)(smem + SM_PHI);
        for (int i = tid; i < 1024; i += 512) d1[i] = s1[i];
        const ull* s2 = (const ull*)(g_gH + (size_t)n * CG * 1024);
        ull* gA = (ull*)(smem + SM_GA);
        ull* gB = (ull*)(smem + SM_GB);
        for (int i = tid; i < 8192; i += 512) {
            ull v = s2[i];
            int j = i >> 8, sq = i & 255;
            int gr = j & 7, half = (j >> 3) & 1;
            ull* arr = (j < 16) ? gA : gB;
            arr[(gr * 260 + sq) * 2 + half] = v;
        }
        const float2* s3 = (const float2*)w_o;
        for (int i = tid; i < 1024; i += 512) {
            int oc = i >> 4, kq = i & 15;
            float2 w = s3[oc * 16 + kq];
            wof[oc * 20 + kq] = pack_h2(w.x * gamma, w.y * gamma);
        }
    }

    int warp = tid >> 5, lane = tid & 31;
    int gr = lane >> 2, q = lane & 3;
    int rXa = warp * 32 + gr;
    int rYa = rXa + 16;

    const uint32_t* tbase = g_thetaH + ((size_t)n * LL + l0) * 4 + q;
    uint32_t tXa = tbase[(size_t)rXa * 4];
    uint32_t tXb = tbase[(size_t)(rXa + 8) * 4];
    uint32_t tYa = tbase[(size_t)rYa * 4];
    uint32_t tYb = tbase[(size_t)(rYa + 8) * 4];
    __syncthreads();

    float c0[4], c1[4], c2[4], c3[4];
    float d0[4], d1[4], d2a[4], d3[4];
#pragma unroll
    for (int i = 0; i < 4; i++) {
        c0[i] = 0.f; c1[i] = 0.f; c2[i] = 0.f; c3[i] = 0.f;
        d0[i] = 0.f; d1[i] = 0.f; d2a[i] = 0.f; d3[i] = 0.f;
    }
    float sX0 = 0.f, sX1 = 0.f, sY0 = 0.f, sY1 = 0.f;

    const char* phiPtr = smem + SM_PHI + (gr * 8 + q * 2) * 4;
    const char* gaPtr  = smem + SM_GA + (gr * 260 + q) * 16;
    const char* gbPtr  = smem + SM_GB + (gr * 260 + q) * 16;

    ull pv = *(const ull*)phiPtr;
    ulonglong2 ga = *(const ulonglong2*)gaPtr;
    ulonglong2 gb = *(const ulonglong2*)gbPtr;

#pragma unroll 1
    for (int s0 = 0; s0 < 64; s0 += 8) {
        uint32_t hX0 = 0u, hX1 = 0u, hY0 = 0u, hY1 = 0u;
#pragma unroll
        for (int si = 0; si < 8; si++) {
            phiPtr += 256; gaPtr += 64; gbPtr += 64;
            ull pvn = *(const ull*)phiPtr;
            ulonglong2 gan = *(const ulonglong2*)gaPtr;
            ulonglong2 gbn = *(const ulonglong2*)gbPtr;

            uint32_t h0[2], h1[2], h2[2], h3[2];
            mma_k8_h(h0, tXa, tXb, (uint32_t)pv);
            mma_k8_h(h1, tXa, tXb, (uint32_t)(pv >> 32));
            mma_k8_h(h2, tYa, tYb, (uint32_t)pv);
            mma_k8_h(h3, tYa, tYb, (uint32_t)(pv >> 32));

            uint32_t a0 = ex2h2(h0[0]);
            uint32_t a1 = ex2h2(h0[1]);
            uint32_t a2 = ex2h2(h1[0]);
            uint32_t a3 = ex2h2(h1[1]);
            uint32_t a4 = ex2h2(h2[0]);
            uint32_t a5 = ex2h2(h2[1]);
            uint32_t a6 = ex2h2(h3[0]);
            uint32_t a7 = ex2h2(h3[1]);

            mma_k16(c0, a0, a1, a2, a3, (uint32_t)ga.x, (uint32_t)(ga.x >> 32));
            mma_k16(c1, a0, a1, a2, a3, (uint32_t)ga.y, (uint32_t)(ga.y >> 32));
            mma_k16(c2, a0, a1, a2, a3, (uint32_t)gb.x, (uint32_t)(gb.x >> 32));
            mma_k16(c3, a0, a1, a2, a3, (uint32_t)gb.y, (uint32_t)(gb.y >> 32));
            mma_k16(d0, a4, a5, a6, a7, (uint32_t)ga.x, (uint32_t)(ga.x >> 32));
            mma_k16(d1, a4, a5, a6, a7, (uint32_t)ga.y, (uint32_t)(ga.y >> 32));
            mma_k16(d2a, a4, a5, a6, a7, (uint32_t)gb.x, (uint32_t)(gb.x >> 32));
            mma_k16(d3, a4, a5, a6, a7, (uint32_t)gb.y, (uint32_t)(gb.y >> 32));

            hX0 = hadd2u(hX0, hadd2u(a0, a2));
            hX1 = hadd2u(hX1, hadd2u(a1, a3));
            hY0 = hadd2u(hY0, hadd2u(a4, a6));
            hY1 = hadd2u(hY1, hadd2u(a5, a7));

            pv = pvn; ga = gan; gb = gbn;
        }
        sX0 += h2sum(hX0); sX1 += h2sum(hX1);
        sY0 += h2sum(hY0); sY1 += h2sum(hY1);
    }

    sX0 += __shfl_xor_sync(0xffffffffu, sX0, 1);
    sX0 += __shfl_xor_sync(0xffffffffu, sX0, 2);
    sX1 += __shfl_xor_sync(0xffffffffu, sX1, 1);
    sX1 += __shfl_xor_sync(0xffffffffu, sX1, 2);
    sY0 += __shfl_xor_sync(0xffffffffu, sY0, 1);
    sY0 += __shfl_xor_sync(0xffffffffu, sY0, 2);
    sY1 += __shfl_xor_sync(0xffffffffu, sY1, 1);
    sY1 += __shfl_xor_sync(0xffffffffu, sY1, 2);

    float invXa = 1.0f / sX0, invXb = 1.0f / sX1;
    float invYa = 1.0f / sY0, invYb = 1.0f / sY1;

    uint32_t eX0 = pack_h2(c0[0] * invXa, c0[1] * invXa);
    uint32_t eX1 = pack_h2(c0[2] * invXb, c0[3] * invXb);
    uint32_t eX2 = pack_h2(c1[0] * invXa, c1[1] * invXa);
    uint32_t eX3 = pack_h2(c1[2] * invXb, c1[3] * invXb);
    uint32_t eX4 = pack_h2(c2[0] * invXa, c2[1] * invXa);
    uint32_t eX5 = pack_h2(c2[2] * invXb, c2[3] * invXb);
    uint32_t eX6 = pack_h2(c3[0] * invXa, c3[1] * invXa);
    uint32_t eX7 = pack_h2(c3[2] * invXb, c3[3] * invXb);
    uint32_t eY0 = pack_h2(d0[0] * invYa, d0[1] * invYa);
    uint32_t eY1 = pack_h2(d0[2] * invYb, d0[3] * invYb);
    uint32_t eY2 = pack_h2(d1[0] * invYa, d1[1] * invYa);
    uint32_t eY3 = pack_h2(d1[2] * invYb, d1[3] * invYb);
    uint32_t eY4 = pack_h2(d2a[0] * invYa, d2a[1] * invYa);
    uint32_t eY5 = pack_h2(d2a[2] * invYb, d2a[3] * invYb);
    uint32_t eY6 = pack_h2(d3[0] * invYa, d3[1] * invYa);
    uint32_t eY7 = pack_h2(d3[2] * invYb, d3[3] * invYb);

    const uint32_t* wrow = wof + gr * 20;
#pragma unroll
    for (int ob = 0; ob < 8; ob++) {
        uint32_t b00 = wrow[ob * 160 + q];
        uint32_t b01 = wrow[ob * 160 + q + 4];
        uint32_t b10 = wrow[ob * 160 + q + 8];
        uint32_t b11 = wrow[ob * 160 + q + 12];

        float fX[4] = {0.f, 0.f, 0.f, 0.f};
        mma_k16(fX, eX0, eX1, eX2, eX3, b00, b01);
        mma_k16(fX, eX4, eX5, eX6, eX7, b10, b11);
        float fY[4] = {0.f, 0.f, 0.f, 0.f};
        mma_k16(fY, eY0, eY1, eY2, eY3, b00, b01);
        mma_k16(fY, eY4, eY5, eY6, eY7, b10, b11);

        int oc = ob * 8 + 2 * q;
        const float* px = x + ((size_t)n * CH + oc) * LL + l0 + rXa;
        float* po = out + ((size_t)n * CH + oc) * LL + l0 + rXa;
        po[0]       = px[0]       + fX[0];
        po[LL]      = px[LL]      + fX[1];
        po[8]       = px[8]       + fX[2];
        po[LL + 8]  = px[LL + 8]  + fX[3];
        po[16]      = px[16]      + fY[0];
        po[LL + 16] = px[LL + 16] + fY[1];
        po[24]      = px[24]      + fY[2];
        po[LL + 24] = px[LL + 24] + fY[3];
    }
}

// ---------------------------------------------------------------------------
extern "C" void kernel_launch(void* const* d_in, const int* in_sizes, int n_in,
                              void* d_out, int out_size) {
    const float* x       = (const float*)d_in[0];
    const float* w_theta = (const float*)d_in[1];
    const float* w_phi   = (const float*)d_in[2];
    const float* w_g     = (const float*)d_in[3];
    const float* w_o     = (const float*)d_in[4];
    const float* gammap  = (const float*)d_in[5];
    float* out = (float*)d_out;

    cudaFuncSetAttribute(proj_mma_kernel, cudaFuncAttributeMaxDynamicSharedMemorySize,
                         PROJ_SMEM);
    cudaFuncSetAttribute(attn_kernel, cudaFuncAttributeMaxDynamicSharedMemorySize,
                         SMEM_SZ);

    proj_mma_kernel<<<128, 512, PROJ_SMEM>>>(x, w_theta, w_phi, w_g);
    dim3 grid(8, NB);
    attn_kernel<<<grid, 512, SMEM_SZ>>>(x, w_o, gammap, out);
}

// round 17
// speedup vs baseline: 1.0517x; 1.0517x over previous
#include <cuda_runtime.h>
#include <cuda_fp16.h>
#include <cstdint>

// Problem constants
#define NB 16
#define CH 64
#define LL 4096   // H*W
#define DD 1024   // pooled locations
#define CK 8      // C>>3 (theta/phi channels)
#define CG 32     // C>>1 (g channels)

typedef unsigned long long ull;

// Scratch (device globals):
//  g_thetaH[n][l][q]  u32 = f16x2 {theta[2q], theta[2q+1]}, pre-scaled by log2(e)
//  g_phiP  [n][4096]  u32, phi fused-B layout: idx = s*64 + gr*8 + q*2 + u
//  g_gH    [n][j][s*4+q][elem] f16, elem -> d = 16s + {2q,2q+1,2q+8,2q+9}
__device__ __align__(16) uint32_t g_thetaH[NB * LL * 4];   // 4 MB
__device__ __align__(16) uint32_t g_phiP[NB * 4096];       // 256 KB
__device__ __align__(16) __half   g_gH[NB * CG * 1024];    // 1 MB

__device__ __forceinline__ ull pk2(float a, float b) {
    ull r; asm("mov.b64 %0, {%1, %2};" : "=l"(r) : "f"(a), "f"(b)); return r;
}
__device__ __forceinline__ float2 upk2(ull v) {
    float2 r; asm("mov.b64 {%0, %1}, %2;" : "=f"(r.x), "=f"(r.y) : "l"(v)); return r;
}
__device__ __forceinline__ ull fma2(ull a, ull b, ull c) {
    ull d; asm("fma.rn.f32x2 %0, %1, %2, %3;" : "=l"(d) : "l"(a), "l"(b), "l"(c)); return d;
}
__device__ __forceinline__ uint32_t pack_h2(float lo, float hi) {
    uint32_t r; asm("cvt.rn.f16x2.f32 %0, %1, %2;" : "=r"(r) : "f"(hi), "f"(lo)); return r;
}
__device__ __forceinline__ uint32_t ex2h2(uint32_t h) {
    uint32_t r; asm("ex2.approx.f16x2 %0, %1;" : "=r"(r) : "r"(h)); return r;
}
__device__ __forceinline__ uint32_t hadd2u(uint32_t a, uint32_t b) {
    uint32_t r; asm("add.f16x2 %0, %1, %2;" : "=r"(r) : "r"(a), "r"(b)); return r;
}
__device__ __forceinline__ float h2sum(uint32_t h) {
    __half2 v = *(__half2*)&h;
    float2 f = __half22float2(v);
    return f.x + f.y;
}

// MMA1: m16n8k8 f16 with f16 accumulator (C=0).
__device__ __forceinline__ void mma_k8_h(uint32_t* d, uint32_t a0, uint32_t a1,
                                         uint32_t b0) {
    asm volatile(
        "mma.sync.aligned.m16n8k8.row.col.f16.f16.f16.f16 "
        "{%0,%1}, {%2,%3}, {%4}, {%5,%6};"
        : "=r"(d[0]), "=r"(d[1])
        : "r"(a0), "r"(a1), "r"(b0), "r"(0u), "r"(0u));
}
// m16n8k16 f16 -> f32 accumulate
__device__ __forceinline__ void mma_k16(float* c, uint32_t a0, uint32_t a1,
                                        uint32_t a2, uint32_t a3,
                                        uint32_t b0, uint32_t b1) {
    asm volatile(
        "mma.sync.aligned.m16n8k16.row.col.f32.f16.f16.f32 "
        "{%0,%1,%2,%3}, {%4,%5,%6,%7}, {%8,%9}, {%0,%1,%2,%3};"
        : "+f"(c[0]), "+f"(c[1]), "+f"(c[2]), "+f"(c[3])
        : "r"(a0), "r"(a1), "r"(a2), "r"(a3), "r"(b0), "r"(b1));
}

// ---------------------------------------------------------------------------
// Fused projection kernel, channel-split: 2 threads per location.
//  h = tid&1:  h0 -> theta(kp0..3) + phi(kp0..3) + g(jp0..3)   (12 rows)
//              h1 -> g(jp4..15)                                 (12 rows)
// Weight table wall[c][24]: rows 0..11 = h0's, 12..23 = h1's.
// 256 CTAs x 512 threads, __launch_bounds__(512,2) -> 2 CTAs/SM, single wave.
// ---------------------------------------------------------------------------
__global__ void __launch_bounds__(512, 2) proj_fused_kernel(
        const float* __restrict__ x, const float* __restrict__ w_theta,
        const float* __restrict__ w_phi, const float* __restrict__ w_g) {
    __shared__ ull wall[64 * 24];   // 12 KB
    int tid = threadIdx.x;

    for (int i = tid; i < 64 * 24; i += 512) {
        int c = i / 24, r = i % 24;
        float w0, w1;
        if (r < 4) {
            w0 = w_theta[(2 * r) * CH + c] * 1.4426950408889634f;
            w1 = w_theta[(2 * r + 1) * CH + c] * 1.4426950408889634f;
        } else if (r < 8) {
            int kp = r - 4;
            w0 = w_phi[(2 * kp) * CH + c];
            w1 = w_phi[(2 * kp + 1) * CH + c];
        } else {
            int jp = r - 8;   // jp 0..15 across both halves
            w0 = w_g[(2 * jp) * CH + c];
            w1 = w_g[(2 * jp + 1) * CH + c];
        }
        wall[c * 24 + r] = pk2(w0, w1);
    }
    __syncthreads();

    int bid = blockIdx.x;
    int n = bid >> 4, yt = bid & 15;
    int h = tid & 1;
    int m = tid >> 1;                  // local location 0..255
    int b0 = m & 1, b1 = (m >> 1) & 1;
    int xpair = (m >> 2) & 31;
    int yp = m >> 7;                   // 0..1
    int y = yt * 4 + yp * 2 + b1;
    int xc = xpair * 2 + b0;
    int l = y * 64 + xc;

    const float* xp = x + ((size_t)n * CH) * LL + l;
    const ull* wbase = wall + h * 12;

    ull acc[12];
#pragma unroll
    for (int r = 0; r < 12; r++) acc[r] = 0ull;

#pragma unroll 8
    for (int c = 0; c < 64; c++) {
        float xv = xp[(size_t)c * LL];
        ull vd = pk2(xv, xv);
        const ull* wr = wbase + c * 24;
#pragma unroll
        for (int r = 0; r < 12; r++) acc[r] = fma2(wr[r], vd, acc[r]);
    }

    // theta store (h0 only; acc[0..3] = theta channel pairs)
    if (h == 0) {
        float2 t0 = upk2(acc[0]), t1 = upk2(acc[1]);
        float2 t2 = upk2(acc[2]), t3 = upk2(acc[3]);
        uint4 tq;
        tq.x = pack_h2(t0.x, t0.y);
        tq.y = pack_h2(t1.x, t1.y);
        tq.z = pack_h2(t2.x, t2.y);
        tq.w = pack_h2(t3.x, t3.y);
        *(uint4*)(g_thetaH + ((size_t)n * LL + l) * 4) = tq;
    }

    // 2x2 max-pool: partners are tid^2 (x) and tid^4 (y); h bit preserved.
    // Pool rows r >= rs (h0 skips theta rows 0..3).
    int rs = h ? 0 : 4;
    float pv[24];
#pragma unroll
    for (int r = 0; r < 12; r++) {
        float2 v = upk2(acc[r]); pv[2 * r] = v.x; pv[2 * r + 1] = v.y;
    }
#pragma unroll
    for (int r = 4; r < 12; r++) {      // always pool rows 4..11
#pragma unroll
        for (int e = 0; e < 2; e++) {
            float v = pv[2 * r + e];
            v = fmaxf(v, __shfl_xor_sync(0xffffffffu, v, 2));
            v = fmaxf(v, __shfl_xor_sync(0xffffffffu, v, 4));
            pv[2 * r + e] = v;
        }
    }
    if (rs == 0) {                      // h1 also pools rows 0..3
#pragma unroll
        for (int r = 0; r < 4; r++) {
#pragma unroll
            for (int e = 0; e < 2; e++) {
                float v = pv[2 * r + e];
                v = fmaxf(v, __shfl_xor_sync(0xffffffffu, v, 2));
                v = fmaxf(v, __shfl_xor_sync(0xffffffffu, v, 4));
                pv[2 * r + e] = v;
            }
        }
    } else {
        // keep warp convergent for the shfl above
#pragma unroll
        for (int r = 0; r < 4; r++) {
#pragma unroll
            for (int e = 0; e < 2; e++) {
                float v = pv[2 * r + e];
                v = fmaxf(v, __shfl_xor_sync(0xffffffffu, v, 2));
                v = fmaxf(v, __shfl_xor_sync(0xffffffffu, v, 4));
            }
        }
    }

    if ((tid & 6) == 0) {               // pool representative (m % 4 == 0)
        int d = (yt * 2 + yp) * 32 + xpair;
        int s = d >> 4, gr8 = d & 7, u = (d >> 3) & 1;
        int qf = (xpair & 7) >> 1;
        int elem = ((xpair >> 3) & 1) * 2 + (xpair & 1);
        __half* gdst = g_gH + (size_t)n * CG * 1024;

        if (h == 0) {
            // phi: rows 4..7 -> pv[8..15], 4 k-pairs
            uint32_t* pdst = g_phiP + (size_t)n * 4096 + s * 64 + gr8 * 8 + u;
            pdst[0] = pack_h2(pv[8], pv[9]);
            pdst[2] = pack_h2(pv[10], pv[11]);
            pdst[4] = pack_h2(pv[12], pv[13]);
            pdst[6] = pack_h2(pv[14], pv[15]);
            // g j0..7: rows 8..11 -> pv[16..23]
#pragma unroll
            for (int j = 0; j < 8; j++)
                gdst[(j * 256 + s * 4 + qf) * 4 + elem] = __float2half_rn(pv[16 + j]);
        } else {
            // g j8..31: rows 0..11 -> pv[0..23]
#pragma unroll
            for (int idx = 0; idx < 24; idx++) {
                int j = 8 + idx;
                gdst[(j * 256 + s * 4 + qf) * 4 + elem] = __float2half_rn(pv[idx]);
            }
        }
    }
}

// ---------------------------------------------------------------------------
// Attention kernel: R13 version verbatim (best measured: 32.6 us).
// M=32 per warp, f16 MMA1, row sums on fma pipe, 8 MMA2s/iter,
// fragment-native epilogue. Grid (8, 16) x 512 = 128 CTAs.
// ---------------------------------------------------------------------------
#define SM_PHI 0
#define SM_GA  16384
#define SM_GB  49664
#define SM_WOF 82944
#define SMEM_SZ 88064

__global__ void __launch_bounds__(512, 1) attn_kernel(
        const float* __restrict__ x, const float* __restrict__ w_o,
        const float* __restrict__ gammap, float* __restrict__ out) {
    extern __shared__ char smem[];
    uint32_t* wof = (uint32_t*)(smem + SM_WOF);

    int tid = threadIdx.x;
    int n = blockIdx.y;
    int l0 = blockIdx.x * 512;
    float gamma = *gammap;

    // Cooperative fills
    {
        const uint4* s1 = (const uint4*)(g_phiP + (size_t)n * 4096);
        uint4* d1 = (uint4*)(smem + SM_PHI);
        for (int i = tid; i < 1024; i += 512) d1[i] = s1[i];
        const ull* s2 = (const ull*)(g_gH + (size_t)n * CG * 1024);
        ull* gA = (ull*)(smem + SM_GA);
        ull* gB = (ull*)(smem + SM_GB);
        for (int i = tid; i < 8192; i += 512) {
            ull v = s2[i];
            int j = i >> 8, sq = i & 255;
            int gr = j & 7, half = (j >> 3) & 1;
            ull* arr = (j < 16) ? gA : gB;
            arr[(gr * 260 + sq) * 2 + half] = v;
        }
        const float2* s3 = (const float2*)w_o;
        for (int i = tid; i < 1024; i += 512) {
            int oc = i >> 4, kq = i & 15;
            float2 w = s3[oc * 16 + kq];
            wof[oc * 20 + kq] = pack_h2(w.x * gamma, w.y * gamma);
        }
    }

    int warp = tid >> 5, lane = tid & 31;
    int gr = lane >> 2, q = lane & 3;
    int rXa = warp * 32 + gr;
    int rYa = rXa + 16;

    const uint32_t* tbase = g_thetaH + ((size_t)n * LL + l0) * 4 + q;
    uint32_t tXa = tbase[(size_t)rXa * 4];
    uint32_t tXb = tbase[(size_t)(rXa + 8) * 4];
    uint32_t tYa = tbase[(size_t)rYa * 4];
    uint32_t tYb = tbase[(size_t)(rYa + 8) * 4];
    __syncthreads();

    float c0[4], c1[4], c2[4], c3[4];
    float d0[4], d1[4], d2a[4], d3[4];
#pragma unroll
    for (int i = 0; i < 4; i++) {
        c0[i] = 0.f; c1[i] = 0.f; c2[i] = 0.f; c3[i] = 0.f;
        d0[i] = 0.f; d1[i] = 0.f; d2a[i] = 0.f; d3[i] = 0.f;
    }
    float sX0 = 0.f, sX1 = 0.f, sY0 = 0.f, sY1 = 0.f;

    const char* phiPtr = smem + SM_PHI + (gr * 8 + q * 2) * 4;
    const char* gaPtr  = smem + SM_GA + (gr * 260 + q) * 16;
    const char* gbPtr  = smem + SM_GB + (gr * 260 + q) * 16;

    ull pv = *(const ull*)phiPtr;
    ulonglong2 ga = *(const ulonglong2*)gaPtr;
    ulonglong2 gb = *(const ulonglong2*)gbPtr;

#pragma unroll 1
    for (int s0 = 0; s0 < 64; s0 += 8) {
        uint32_t hX0 = 0u, hX1 = 0u, hY0 = 0u, hY1 = 0u;
#pragma unroll
        for (int si = 0; si < 8; si++) {
            phiPtr += 256; gaPtr += 64; gbPtr += 64;
            ull pvn = *(const ull*)phiPtr;
            ulonglong2 gan = *(const ulonglong2*)gaPtr;
            ulonglong2 gbn = *(const ulonglong2*)gbPtr;

            uint32_t h0[2], h1[2], h2[2], h3[2];
            mma_k8_h(h0, tXa, tXb, (uint32_t)pv);
            mma_k8_h(h1, tXa, tXb, (uint32_t)(pv >> 32));
            mma_k8_h(h2, tYa, tYb, (uint32_t)pv);
            mma_k8_h(h3, tYa, tYb, (uint32_t)(pv >> 32));

            uint32_t a0 = ex2h2(h0[0]);
            uint32_t a1 = ex2h2(h0[1]);
            uint32_t a2 = ex2h2(h1[0]);
            uint32_t a3 = ex2h2(h1[1]);
            uint32_t a4 = ex2h2(h2[0]);
            uint32_t a5 = ex2h2(h2[1]);
            uint32_t a6 = ex2h2(h3[0]);
            uint32_t a7 = ex2h2(h3[1]);

            mma_k16(c0, a0, a1, a2, a3, (uint32_t)ga.x, (uint32_t)(ga.x >> 32));
            mma_k16(c1, a0, a1, a2, a3, (uint32_t)ga.y, (uint32_t)(ga.y >> 32));
            mma_k16(c2, a0, a1, a2, a3, (uint32_t)gb.x, (uint32_t)(gb.x >> 32));
            mma_k16(c3, a0, a1, a2, a3, (uint32_t)gb.y, (uint32_t)(gb.y >> 32));
            mma_k16(d0, a4, a5, a6, a7, (uint32_t)ga.x, (uint32_t)(ga.x >> 32));
            mma_k16(d1, a4, a5, a6, a7, (uint32_t)ga.y, (uint32_t)(ga.y >> 32));
            mma_k16(d2a, a4, a5, a6, a7, (uint32_t)gb.x, (uint32_t)(gb.x >> 32));
            mma_k16(d3, a4, a5, a6, a7, (uint32_t)gb.y, (uint32_t)(gb.y >> 32));

            hX0 = hadd2u(hX0, hadd2u(a0, a2));
            hX1 = hadd2u(hX1, hadd2u(a1, a3));
            hY0 = hadd2u(hY0, hadd2u(a4, a6));
            hY1 = hadd2u(hY1, hadd2u(a5, a7));

            pv = pvn; ga = gan; gb = gbn;
        }
        sX0 += h2sum(hX0); sX1 += h2sum(hX1);
        sY0 += h2sum(hY0); sY1 += h2sum(hY1);
    }

    sX0 += __shfl_xor_sync(0xffffffffu, sX0, 1);
    sX0 += __shfl_xor_sync(0xffffffffu, sX0, 2);
    sX1 += __shfl_xor_sync(0xffffffffu, sX1, 1);
    sX1 += __shfl_xor_sync(0xffffffffu, sX1, 2);
    sY0 += __shfl_xor_sync(0xffffffffu, sY0, 1);
    sY0 += __shfl_xor_sync(0xffffffffu, sY0, 2);
    sY1 += __shfl_xor_sync(0xffffffffu, sY1, 1);
    sY1 += __shfl_xor_sync(0xffffffffu, sY1, 2);

    float invXa = 1.0f / sX0, invXb = 1.0f / sX1;
    float invYa = 1.0f / sY0, invYb = 1.0f / sY1;

    uint32_t eX0 = pack_h2(c0[0] * invXa, c0[1] * invXa);
    uint32_t eX1 = pack_h2(c0[2] * invXb, c0[3] * invXb);
    uint32_t eX2 = pack_h2(c1[0] * invXa, c1[1] * invXa);
    uint32_t eX3 = pack_h2(c1[2] * invXb, c1[3] * invXb);
    uint32_t eX4 = pack_h2(c2[0] * invXa, c2[1] * invXa);
    uint32_t eX5 = pack_h2(c2[2] * invXb, c2[3] * invXb);
    uint32_t eX6 = pack_h2(c3[0] * invXa, c3[1] * invXa);
    uint32_t eX7 = pack_h2(c3[2] * invXb, c3[3] * invXb);
    uint32_t eY0 = pack_h2(d0[0] * invYa, d0[1] * invYa);
    uint32_t eY1 = pack_h2(d0[2] * invYb, d0[3] * invYb);
    uint32_t eY2 = pack_h2(d1[0] * invYa, d1[1] * invYa);
    uint32_t eY3 = pack_h2(d1[2] * invYb, d1[3] * invYb);
    uint32_t eY4 = pack_h2(d2a[0] * invYa, d2a[1] * invYa);
    uint32_t eY5 = pack_h2(d2a[2] * invYb, d2a[3] * invYb);
    uint32_t eY6 = pack_h2(d3[0] * invYa, d3[1] * invYa);
    uint32_t eY7 = pack_h2(d3[2] * invYb, d3[3] * invYb);

    const uint32_t* wrow = wof + gr * 20;
#pragma unroll
    for (int ob = 0; ob < 8; ob++) {
        uint32_t b00 = wrow[ob * 160 + q];
        uint32_t b01 = wrow[ob * 160 + q + 4];
        uint32_t b10 = wrow[ob * 160 + q + 8];
        uint32_t b11 = wrow[ob * 160 + q + 12];

        float fX[4] = {0.f, 0.f, 0.f, 0.f};
        mma_k16(fX, eX0, eX1, eX2, eX3, b00, b01);
        mma_k16(fX, eX4, eX5, eX6, eX7, b10, b11);
        float fY[4] = {0.f, 0.f, 0.f, 0.f};
        mma_k16(fY, eY0, eY1, eY2, eY3, b00, b01);
        mma_k16(fY, eY4, eY5, eY6, eY7, b10, b11);

        int oc = ob * 8 + 2 * q;
        const float* px = x + ((size_t)n * CH + oc) * LL + l0 + rXa;
        float* po = out + ((size_t)n * CH + oc) * LL + l0 + rXa;
        po[0]       = px[0]       + fX[0];
        po[LL]      = px[LL]      + fX[1];
        po[8]       = px[8]       + fX[2];
        po[LL + 8]  = px[LL + 8]  + fX[3];
        po[16]      = px[16]      + fY[0];
        po[LL + 16] = px[LL + 16] + fY[1];
        po[24]      = px[24]      + fY[2];
        po[LL + 24] = px[LL + 24] + fY[3];
    }
}

// ---------------------------------------------------------------------------
extern "C" void kernel_launch(void* const* d_in, const int* in_sizes, int n_in,
                              void* d_out, int out_size) {
    const float* x       = (const float*)d_in[0];
    const float* w_theta = (const float*)d_in[1];
    const float* w_phi   = (const float*)d_in[2];
    const float* w_g     = (const float*)d_in[3];
    const float* w_o     = (const float*)d_in[4];
    const float* gammap  = (const float*)d_in[5];
    float* out = (float*)d_out;

    cudaFuncSetAttribute(attn_kernel, cudaFuncAttributeMaxDynamicSharedMemorySize,
                         SMEM_SZ);

    proj_fused_kernel<<<NB * 16, 512>>>(x, w_theta, w_phi, w_g);
    dim3 grid(8, NB);
    attn_kernel<<<grid, 512, SMEM_SZ>>>(x, w_o, gammap, out);
}